// round 14
// baseline (speedup 1.0000x reference)
#include <cuda_runtime.h>
#include <cuda_bf16.h>
#include <mma.h>
#include <cstdint>

using namespace nvcuda;

// Problem constants
#define EMBED  1024
#define NHEADS 16
#define HDIM   64
#define BATCH  4
#define SEQ    2048
#define MTOK   (BATCH * SEQ)   // 8192
#define QKV_PLANE (BATCH * NHEADS * SEQ * HDIM)   // 8388608 elems
#define ATT_PLANE (MTOK * EMBED)                  // 8388608 elems

// ---------------------------------------------------------------------------
// Scratch — proven-safe 128 MB footprint, planes recycled (R13 scheme):
//  g_q/g_k/g_v: QKV output bf16 hi[0:8M)/lo[8M:16M) planes
//  g_attn: phase1 = qkv_w planes; phase2 = attn-out planes
//  g_q:    phase3 (after attn) = out_w planes
// ---------------------------------------------------------------------------
__device__ float g_q[QKV_PLANE];
__device__ float g_k[QKV_PLANE];
__device__ float g_v[QKV_PLANE];
__device__ float g_attn[ATT_PLANE];

__device__ __forceinline__ void sp_bf16(float x, __nv_bfloat16& h, __nv_bfloat16& l)
{
    h = __float2bfloat16_rn(x);
    l = __float2bfloat16_rn(x - __bfloat162float(h));
}

__device__ __forceinline__ void st_split4(
    __nv_bfloat16* H, __nv_bfloat16* L, int off, float4 v)
{
    __nv_bfloat16 hx, lx, hy, ly, hz, lz, hw, lw;
    sp_bf16(v.x, hx, lx); sp_bf16(v.y, hy, ly);
    sp_bf16(v.z, hz, lz); sp_bf16(v.w, hw, lw);
    *(__nv_bfloat162*)(H + off)     = __nv_bfloat162(hx, hy);
    *(__nv_bfloat162*)(H + off + 2) = __nv_bfloat162(hz, hw);
    *(__nv_bfloat162*)(L + off)     = __nv_bfloat162(lx, ly);
    *(__nv_bfloat162*)(L + off + 2) = __nv_bfloat162(lz, lw);
}

__global__ __launch_bounds__(256) void split_w(
    const float* __restrict__ src,
    __nv_bfloat16* __restrict__ hp, __nv_bfloat16* __restrict__ lp)
{
    int i = blockIdx.x * 256 + threadIdx.x;
    float4 v = ((const float4*)src)[i];
    st_split4(hp, lp, 4 * i, v);
}

// ---------------------------------------------------------------------------
// GEMM geometry: block tile 64(m) x 128(n), BK=32, 128 threads (4 warps,
// wm = w&1, wn = w>>1; warp tile 32x64). 2 CTAs/SM (launch_bounds 128,2).
// smem/CTA: buffers 2 x (Ah|Al 64x40 + Bh|Bl 128x40) bf16 = 61440 B
//           + patch 4 x 16 x 20 f32 = 5120 B  -> 66560 B.
// ---------------------------------------------------------------------------
#define LDSG   40
#define AMAT   (64 * LDSG)                  // 2560 elems
#define BMAT   (128 * LDSG)                 // 5120 elems
#define BUFE   (2 * AMAT + 2 * BMAT)        // 15360 elems (30720 B)
#define GEMM_SMEM (2 * BUFE * 2 + 4 * 16 * 20 * 4)   // 66560 B
#define NKBG   (EMBED / 32)                 // 32

// ---------------------------------------------------------------------------
// QKV GEMM: A = x fp32 (in-kernel split), B = pre-split planes.
// Epilogue writes bf16 hi/lo planes into g_q/g_k/g_v.
// ---------------------------------------------------------------------------
__global__ __launch_bounds__(128, 2) void gemm_qkv(
    const float* __restrict__ A, const __nv_bfloat16* __restrict__ Wh,
    const float* __restrict__ bias)
{
    extern __shared__ __align__(16) char dsm[];
    __nv_bfloat16* sm0 = (__nv_bfloat16*)dsm;
    float* sPatchAll   = (float*)(dsm + 2 * BUFE * 2);

    const __nv_bfloat16* Wl = Wh + 3 * EMBED * EMBED;

    const int tid  = threadIdx.x;
    const int lane = tid & 31;
    const int w    = tid >> 5;
    const int wm   = w & 1;
    const int wn   = w >> 1;
    const int m0   = blockIdx.y * 64;
    const int n0   = blockIdx.x * 128;

    // A loader: 64 rows, 2 threads/row, 16 floats each (4 float4)
    const int arow = tid >> 1;
    const int aseg = (tid & 1) * 16;
    const float* gA = A + (size_t)(m0 + arow) * EMBED + aseg;
    // B loader: 128 rows, 1 thread/row, whole 32-elem row (4 uint4) per plane
    const __nv_bfloat16* gWh = Wh + (size_t)(n0 + tid) * EMBED;
    const __nv_bfloat16* gWl = Wl + (size_t)(n0 + tid) * EMBED;

    wmma::fragment<wmma::accumulator, 16, 16, 16, float> acc[2][4];
#pragma unroll
    for (int mt = 0; mt < 2; mt++)
#pragma unroll
        for (int nt = 0; nt < 4; nt++)
            wmma::fill_fragment(acc[mt][nt], 0.0f);

    float4 pa[4];
    uint4  ph[4], pl[4];

    // prologue -> buffer 0
#pragma unroll
    for (int j = 0; j < 4; j++) pa[j] = *(const float4*)(gA + 4 * j);
#pragma unroll
    for (int j = 0; j < 4; j++) {
        ph[j] = *(const uint4*)(gWh + 8 * j);
        pl[j] = *(const uint4*)(gWl + 8 * j);
    }
    {
        __nv_bfloat16* bAh = sm0;
        __nv_bfloat16* bAl = sm0 + AMAT;
        __nv_bfloat16* bBh = sm0 + 2 * AMAT;
        __nv_bfloat16* bBl = sm0 + 2 * AMAT + BMAT;
        const int aoff = arow * LDSG + aseg;
#pragma unroll
        for (int j = 0; j < 4; j++) st_split4(bAh, bAl, aoff + 4 * j, pa[j]);
        const int boff = tid * LDSG;
#pragma unroll
        for (int j = 0; j < 4; j++) {
            *(uint4*)(bBh + boff + 8 * j) = ph[j];
            *(uint4*)(bBl + boff + 8 * j) = pl[j];
        }
    }
    __syncthreads();

    for (int kb = 0; kb < NKBG; kb++) {
        if (kb + 1 < NKBG) {
            const int g = (kb + 1) * 32;
#pragma unroll
            for (int j = 0; j < 4; j++) pa[j] = *(const float4*)(gA + g + 4 * j);
#pragma unroll
            for (int j = 0; j < 4; j++) {
                ph[j] = *(const uint4*)(gWh + g + 8 * j);
                pl[j] = *(const uint4*)(gWl + g + 8 * j);
            }
        }

        const __nv_bfloat16* sb  = sm0 + (kb & 1) * BUFE;
        const __nv_bfloat16* sAh = sb;
        const __nv_bfloat16* sAl = sb + AMAT;
        const __nv_bfloat16* sBh = sb + 2 * AMAT;
        const __nv_bfloat16* sBl = sb + 2 * AMAT + BMAT;
#pragma unroll
        for (int ks = 0; ks < 2; ks++) {
            const int kk = ks * 16;
            wmma::fragment<wmma::matrix_a, 16, 16, 16, __nv_bfloat16,
                           wmma::row_major> ah[2], al[2];
#pragma unroll
            for (int mt = 0; mt < 2; mt++) {
                wmma::load_matrix_sync(ah[mt], sAh + (wm * 32 + mt * 16) * LDSG + kk, LDSG);
                wmma::load_matrix_sync(al[mt], sAl + (wm * 32 + mt * 16) * LDSG + kk, LDSG);
            }
#pragma unroll
            for (int nt = 0; nt < 4; nt++) {
                wmma::fragment<wmma::matrix_b, 16, 16, 16, __nv_bfloat16,
                               wmma::col_major> bh, bl;
                wmma::load_matrix_sync(bh, sBh + (wn * 64 + nt * 16) * LDSG + kk, LDSG);
                wmma::load_matrix_sync(bl, sBl + (wn * 64 + nt * 16) * LDSG + kk, LDSG);
#pragma unroll
                for (int mt = 0; mt < 2; mt++) {
                    wmma::mma_sync(acc[mt][nt], ah[mt], bh, acc[mt][nt]);
                    wmma::mma_sync(acc[mt][nt], ah[mt], bl, acc[mt][nt]);
                    wmma::mma_sync(acc[mt][nt], al[mt], bh, acc[mt][nt]);
                }
            }
        }

        if (kb + 1 < NKBG) {
            __nv_bfloat16* bb  = sm0 + ((kb + 1) & 1) * BUFE;
            __nv_bfloat16* bAh = bb;
            __nv_bfloat16* bAl = bb + AMAT;
            __nv_bfloat16* bBh = bb + 2 * AMAT;
            __nv_bfloat16* bBl = bb + 2 * AMAT + BMAT;
            const int aoff = arow * LDSG + aseg;
#pragma unroll
            for (int j = 0; j < 4; j++) st_split4(bAh, bAl, aoff + 4 * j, pa[j]);
            const int boff = tid * LDSG;
#pragma unroll
            for (int j = 0; j < 4; j++) {
                *(uint4*)(bBh + boff + 8 * j) = ph[j];
                *(uint4*)(bBl + boff + 8 * j) = pl[j];
            }
            __syncthreads();
        }
    }

    // Epilogue: bias, then write bf16 hi/lo planes into g_q/g_k/g_v
    float* patch = sPatchAll + w * 320;
    const int pr = lane >> 1;
    const int pc = (lane & 1) * 8;
#pragma unroll
    for (int mt = 0; mt < 2; mt++)
#pragma unroll
        for (int nt = 0; nt < 4; nt++) {
            wmma::store_matrix_sync(patch, acc[mt][nt], 20, wmma::mem_row_major);
            __syncwarp();
            const int m = m0 + wm * 32 + mt * 16 + pr;
            const int n = n0 + wn * 64 + nt * 16 + pc;
            float f[8];
#pragma unroll
            for (int j = 0; j < 8; j++)
                f[j] = patch[pr * 20 + pc + j] + bias[n + j];
            const int b_ = m >> 11, nq = m & (SEQ - 1);
            const int which = n >> 10, e = n & 1023;
            const int h = e >> 6, d = e & 63;
            float* base = (which == 0) ? g_q : (which == 1) ? g_k : g_v;
            __nv_bfloat16* hp = (__nv_bfloat16*)base;
            __nv_bfloat16* lp = hp + QKV_PLANE;
            const size_t off = ((((size_t)b_ * NHEADS) + h) * SEQ + nq) * HDIM + d;
#pragma unroll
            for (int j = 0; j < 8; j += 2) {
                __nv_bfloat16 h0, l0, h1, l1;
                sp_bf16(f[j], h0, l0);
                sp_bf16(f[j + 1], h1, l1);
                *(__nv_bfloat162*)(hp + off + j) = __nv_bfloat162(h0, h1);
                *(__nv_bfloat162*)(lp + off + j) = __nv_bfloat162(l0, l1);
            }
            __syncwarp();
        }
}

// ---------------------------------------------------------------------------
// Output-proj GEMM: both operands pre-split planes; zero in-loop conversions.
// ---------------------------------------------------------------------------
__global__ __launch_bounds__(128, 2) void gemm_proj(
    const __nv_bfloat16* __restrict__ Ah, const __nv_bfloat16* __restrict__ Wh,
    const float* __restrict__ bias, float* __restrict__ C)
{
    extern __shared__ __align__(16) char dsm[];
    __nv_bfloat16* sm0 = (__nv_bfloat16*)dsm;
    float* sPatchAll   = (float*)(dsm + 2 * BUFE * 2);

    const __nv_bfloat16* Al = Ah + ATT_PLANE;
    const __nv_bfloat16* Wl = Wh + EMBED * EMBED;

    const int tid  = threadIdx.x;
    const int lane = tid & 31;
    const int w    = tid >> 5;
    const int wm   = w & 1;
    const int wn   = w >> 1;
    const int m0   = blockIdx.y * 64;
    const int n0   = blockIdx.x * 128;

    const int arow = tid >> 1;
    const int aseg = (tid & 1) * 16;
    const __nv_bfloat16* gAh = Ah + (size_t)(m0 + arow) * EMBED + aseg;
    const __nv_bfloat16* gAl = Al + (size_t)(m0 + arow) * EMBED + aseg;
    const __nv_bfloat16* gWh = Wh + (size_t)(n0 + tid) * EMBED;
    const __nv_bfloat16* gWl = Wl + (size_t)(n0 + tid) * EMBED;

    wmma::fragment<wmma::accumulator, 16, 16, 16, float> acc[2][4];
#pragma unroll
    for (int mt = 0; mt < 2; mt++)
#pragma unroll
        for (int nt = 0; nt < 4; nt++)
            wmma::fill_fragment(acc[mt][nt], 0.0f);

    uint4 pa[2], pA[2], ph[4], pl[4];

    pa[0] = *(const uint4*)(gAh);      pa[1] = *(const uint4*)(gAh + 8);
    pA[0] = *(const uint4*)(gAl);      pA[1] = *(const uint4*)(gAl + 8);
#pragma unroll
    for (int j = 0; j < 4; j++) {
        ph[j] = *(const uint4*)(gWh + 8 * j);
        pl[j] = *(const uint4*)(gWl + 8 * j);
    }
    {
        __nv_bfloat16* b = sm0;
        const int aoff = arow * LDSG + aseg;
        *(uint4*)(b + aoff) = pa[0];               *(uint4*)(b + aoff + 8) = pa[1];
        *(uint4*)(b + AMAT + aoff) = pA[0];        *(uint4*)(b + AMAT + aoff + 8) = pA[1];
        const int boff = tid * LDSG;
#pragma unroll
        for (int j = 0; j < 4; j++) {
            *(uint4*)(b + 2 * AMAT + boff + 8 * j)        = ph[j];
            *(uint4*)(b + 2 * AMAT + BMAT + boff + 8 * j) = pl[j];
        }
    }
    __syncthreads();

    for (int kb = 0; kb < NKBG; kb++) {
        if (kb + 1 < NKBG) {
            const int g = (kb + 1) * 32;
            pa[0] = *(const uint4*)(gAh + g);  pa[1] = *(const uint4*)(gAh + g + 8);
            pA[0] = *(const uint4*)(gAl + g);  pA[1] = *(const uint4*)(gAl + g + 8);
#pragma unroll
            for (int j = 0; j < 4; j++) {
                ph[j] = *(const uint4*)(gWh + g + 8 * j);
                pl[j] = *(const uint4*)(gWl + g + 8 * j);
            }
        }

        const __nv_bfloat16* sb  = sm0 + (kb & 1) * BUFE;
        const __nv_bfloat16* sAh = sb;
        const __nv_bfloat16* sAl = sb + AMAT;
        const __nv_bfloat16* sBh = sb + 2 * AMAT;
        const __nv_bfloat16* sBl = sb + 2 * AMAT + BMAT;
#pragma unroll
        for (int ks = 0; ks < 2; ks++) {
            const int kk = ks * 16;
            wmma::fragment<wmma::matrix_a, 16, 16, 16, __nv_bfloat16,
                           wmma::row_major> ah[2], al[2];
#pragma unroll
            for (int mt = 0; mt < 2; mt++) {
                wmma::load_matrix_sync(ah[mt], sAh + (wm * 32 + mt * 16) * LDSG + kk, LDSG);
                wmma::load_matrix_sync(al[mt], sAl + (wm * 32 + mt * 16) * LDSG + kk, LDSG);
            }
#pragma unroll
            for (int nt = 0; nt < 4; nt++) {
                wmma::fragment<wmma::matrix_b, 16, 16, 16, __nv_bfloat16,
                               wmma::col_major> bh, bl;
                wmma::load_matrix_sync(bh, sBh + (wn * 64 + nt * 16) * LDSG + kk, LDSG);
                wmma::load_matrix_sync(bl, sBl + (wn * 64 + nt * 16) * LDSG + kk, LDSG);
#pragma unroll
                for (int mt = 0; mt < 2; mt++) {
                    wmma::mma_sync(acc[mt][nt], ah[mt], bh, acc[mt][nt]);
                    wmma::mma_sync(acc[mt][nt], ah[mt], bl, acc[mt][nt]);
                    wmma::mma_sync(acc[mt][nt], al[mt], bh, acc[mt][nt]);
                }
            }
        }

        if (kb + 1 < NKBG) {
            __nv_bfloat16* b = sm0 + ((kb + 1) & 1) * BUFE;
            const int aoff = arow * LDSG + aseg;
            *(uint4*)(b + aoff) = pa[0];               *(uint4*)(b + aoff + 8) = pa[1];
            *(uint4*)(b + AMAT + aoff) = pA[0];        *(uint4*)(b + AMAT + aoff + 8) = pA[1];
            const int boff = tid * LDSG;
#pragma unroll
            for (int j = 0; j < 4; j++) {
                *(uint4*)(b + 2 * AMAT + boff + 8 * j)        = ph[j];
                *(uint4*)(b + 2 * AMAT + BMAT + boff + 8 * j) = pl[j];
            }
            __syncthreads();
        }
    }

    float* patch = sPatchAll + w * 320;
    const int pr = lane >> 1;
    const int pc = (lane & 1) * 8;
#pragma unroll
    for (int mt = 0; mt < 2; mt++)
#pragma unroll
        for (int nt = 0; nt < 4; nt++) {
            wmma::store_matrix_sync(patch, acc[mt][nt], 20, wmma::mem_row_major);
            __syncwarp();
            const int m = m0 + wm * 32 + mt * 16 + pr;
            const int n = n0 + wn * 64 + nt * 16 + pc;
            float4 q0 = *(const float4*)&patch[pr * 20 + pc];
            float4 q1 = *(const float4*)&patch[pr * 20 + pc + 4];
            float4 b0 = *(const float4*)&bias[n];
            float4 b1 = *(const float4*)&bias[n + 4];
            q0.x += b0.x; q0.y += b0.y; q0.z += b0.z; q0.w += b0.w;
            q1.x += b1.x; q1.y += b1.y; q1.z += b1.z; q1.w += b1.w;
            float* p = C + (size_t)m * EMBED + n;
            *(float4*)(p)     = q0;
            *(float4*)(p + 4) = q1;
            __syncwarp();
        }
}

// ---------------------------------------------------------------------------
// WMMA flash attention — byte-identical to Round 13 (passing).
// ---------------------------------------------------------------------------
#define OFF_QH 0
#define OFF_QL 18432
#define OFF_KH 36864
#define OFF_KL 55296
#define OFF_VH 73728
#define OFF_VL 92160
#define OFF_S  110592
#define OFF_PH 110592
#define OFF_PL 145408
#define OFF_OS 180224
#define ATTN_SMEM_BYTES 215040

__global__ __launch_bounds__(256, 1) void attn_wmma()
{
    extern __shared__ char smc[];
    __nv_bfloat16* Qh = (__nv_bfloat16*)(smc + OFF_QH);
    __nv_bfloat16* Ql = (__nv_bfloat16*)(smc + OFF_QL);
    __nv_bfloat16* Kh = (__nv_bfloat16*)(smc + OFF_KH);
    __nv_bfloat16* Kl = (__nv_bfloat16*)(smc + OFF_KL);
    __nv_bfloat16* Vh = (__nv_bfloat16*)(smc + OFF_VH);
    __nv_bfloat16* Vl = (__nv_bfloat16*)(smc + OFF_VL);
    float*         S  = (float*)        (smc + OFF_S);
    __nv_bfloat16* Ph = (__nv_bfloat16*)(smc + OFF_PH);
    __nv_bfloat16* Pl = (__nv_bfloat16*)(smc + OFF_PL);
    float*         Os = (float*)        (smc + OFF_OS);

    const int tid  = threadIdx.x;
    const int w    = tid >> 5;
    const int wm   = w & 3;
    const int wn   = w >> 2;
    const int ty   = tid >> 4;
    const int tx   = tid & 15;
    const int bh   = blockIdx.y;
    const int q0   = blockIdx.x * 128;

    const __nv_bfloat16* qh = (const __nv_bfloat16*)g_q;
    const __nv_bfloat16* kh = (const __nv_bfloat16*)g_k;
    const __nv_bfloat16* vh = (const __nv_bfloat16*)g_v;
    const size_t tb = (size_t)bh * SEQ * HDIM;

#pragma unroll
    for (int i = 0; i < 4; i++) {
        int idx = tid + i * 256;
        int r   = idx >> 3;
        int c8  = (idx & 7) * 8;
        size_t g = tb + (size_t)(q0 + r) * HDIM + c8;
        *(uint4*)(Qh + r * 72 + c8) = *(const uint4*)(qh + g);
        *(uint4*)(Ql + r * 72 + c8) = *(const uint4*)(qh + QKV_PLANE + g);
    }

    float m_r[8], l_r[8], corr[8], o[8][4];
#pragma unroll
    for (int i = 0; i < 8; i++) {
        m_r[i] = -1e30f;
        l_r[i] = 0.f;
#pragma unroll
        for (int j = 0; j < 4; j++) o[i][j] = 0.f;
    }
    __syncthreads();

    for (int t = 0; t < SEQ / 128; t++) {
        const int k0 = t * 128;
#pragma unroll
        for (int i = 0; i < 4; i++) {
            int idx = tid + i * 256;
            int r   = idx >> 3;
            int c8  = (idx & 7) * 8;
            size_t g = tb + (size_t)(k0 + r) * HDIM + c8;
            *(uint4*)(Kh + r * 72 + c8) = *(const uint4*)(kh + g);
            *(uint4*)(Kl + r * 72 + c8) = *(const uint4*)(kh + QKV_PLANE + g);
            *(uint4*)(Vh + r * 72 + c8) = *(const uint4*)(vh + g);
            *(uint4*)(Vl + r * 72 + c8) = *(const uint4*)(vh + QKV_PLANE + g);
        }
        __syncthreads();

        {
            wmma::fragment<wmma::accumulator, 16, 16, 16, float> accS[2][4];
#pragma unroll
            for (int mt = 0; mt < 2; mt++)
#pragma unroll
                for (int nt = 0; nt < 4; nt++)
                    wmma::fill_fragment(accS[mt][nt], 0.0f);

#pragma unroll
            for (int kk = 0; kk < 4; kk++) {
                const int k = kk * 16;
                wmma::fragment<wmma::matrix_a, 16, 16, 16, __nv_bfloat16,
                               wmma::row_major> ah[2], al[2];
#pragma unroll
                for (int mt = 0; mt < 2; mt++) {
                    wmma::load_matrix_sync(ah[mt], &Qh[(wm * 32 + mt * 16) * 72 + k], 72);
                    wmma::load_matrix_sync(al[mt], &Ql[(wm * 32 + mt * 16) * 72 + k], 72);
                }
#pragma unroll
                for (int nt = 0; nt < 4; nt++) {
                    wmma::fragment<wmma::matrix_b, 16, 16, 16, __nv_bfloat16,
                                   wmma::col_major> bh2, bl2;
                    wmma::load_matrix_sync(bh2, &Kh[(wn * 64 + nt * 16) * 72 + k], 72);
                    wmma::load_matrix_sync(bl2, &Kl[(wn * 64 + nt * 16) * 72 + k], 72);
#pragma unroll
                    for (int mt = 0; mt < 2; mt++) {
                        wmma::mma_sync(accS[mt][nt], ah[mt], bh2, accS[mt][nt]);
                        wmma::mma_sync(accS[mt][nt], ah[mt], bl2, accS[mt][nt]);
                        wmma::mma_sync(accS[mt][nt], al[mt], bh2, accS[mt][nt]);
                    }
                }
            }
#pragma unroll
            for (int mt = 0; mt < 2; mt++)
#pragma unroll
                for (int nt = 0; nt < 4; nt++)
                    wmma::store_matrix_sync(
                        &S[(wm * 32 + mt * 16) * 136 + wn * 64 + nt * 16],
                        accS[mt][nt], 136, wmma::mem_row_major);
        }
        __syncthreads();

        float s[8][8];
#pragma unroll
        for (int r = 0; r < 8; r++) {
            *(float4*)&s[r][0] = *(const float4*)&S[(ty * 8 + r) * 136 + tx * 8];
            *(float4*)&s[r][4] = *(const float4*)&S[(ty * 8 + r) * 136 + tx * 8 + 4];
        }
#pragma unroll
        for (int r = 0; r < 8; r++) {
            float tmax = -1e30f;
#pragma unroll
            for (int c = 0; c < 8; c++) {
                s[r][c] *= 0.125f;
                tmax = fmaxf(tmax, s[r][c]);
            }
#pragma unroll
            for (int off = 8; off; off >>= 1)
                tmax = fmaxf(tmax, __shfl_xor_sync(0xffffffffu, tmax, off));
            float mnew = fmaxf(m_r[r], tmax);
            corr[r] = __expf(m_r[r] - mnew);
            m_r[r] = mnew;
            float rsum = 0.f;
#pragma unroll
            for (int c = 0; c < 8; c++) {
                float p = __expf(s[r][c] - mnew);
                s[r][c] = p;
                rsum += p;
            }
#pragma unroll
            for (int off = 8; off; off >>= 1)
                rsum += __shfl_xor_sync(0xffffffffu, rsum, off);
            l_r[r] = l_r[r] * corr[r] + rsum;
        }
        __syncthreads();

#pragma unroll
        for (int r = 0; r < 8; r++)
#pragma unroll
            for (int c = 0; c < 8; c++) {
                __nv_bfloat16 h, l;
                sp_bf16(s[r][c], h, l);
                Ph[(ty * 8 + r) * 136 + tx * 8 + c] = h;
                Pl[(ty * 8 + r) * 136 + tx * 8 + c] = l;
            }
        __syncthreads();

        {
            wmma::fragment<wmma::accumulator, 16, 16, 16, float> accO[2][2];
#pragma unroll
            for (int mt = 0; mt < 2; mt++)
#pragma unroll
                for (int nt = 0; nt < 2; nt++)
                    wmma::fill_fragment(accO[mt][nt], 0.0f);

#pragma unroll
            for (int kk = 0; kk < 8; kk++) {
                const int k = kk * 16;
                wmma::fragment<wmma::matrix_a, 16, 16, 16, __nv_bfloat16,
                               wmma::row_major> ph[2], pl[2];
#pragma unroll
                for (int mt = 0; mt < 2; mt++) {
                    wmma::load_matrix_sync(ph[mt], &Ph[(wm * 32 + mt * 16) * 136 + k], 136);
                    wmma::load_matrix_sync(pl[mt], &Pl[(wm * 32 + mt * 16) * 136 + k], 136);
                }
#pragma unroll
                for (int nt = 0; nt < 2; nt++) {
                    wmma::fragment<wmma::matrix_b, 16, 16, 16, __nv_bfloat16,
                                   wmma::row_major> vbh, vbl;
                    wmma::load_matrix_sync(vbh, &Vh[k * 72 + wn * 32 + nt * 16], 72);
                    wmma::load_matrix_sync(vbl, &Vl[k * 72 + wn * 32 + nt * 16], 72);
#pragma unroll
                    for (int mt = 0; mt < 2; mt++) {
                        wmma::mma_sync(accO[mt][nt], ph[mt], vbh, accO[mt][nt]);
                        wmma::mma_sync(accO[mt][nt], ph[mt], vbl, accO[mt][nt]);
                        wmma::mma_sync(accO[mt][nt], pl[mt], vbh, accO[mt][nt]);
                    }
                }
            }
#pragma unroll
            for (int mt = 0; mt < 2; mt++)
#pragma unroll
                for (int nt = 0; nt < 2; nt++)
                    wmma::store_matrix_sync(
                        &Os[(wm * 32 + mt * 16) * 68 + wn * 32 + nt * 16],
                        accO[mt][nt], 68, wmma::mem_row_major);
        }
        __syncthreads();

#pragma unroll
        for (int r = 0; r < 8; r++) {
            float4 pv = *(const float4*)&Os[(ty * 8 + r) * 68 + tx * 4];
            o[r][0] = o[r][0] * corr[r] + pv.x;
            o[r][1] = o[r][1] * corr[r] + pv.y;
            o[r][2] = o[r][2] * corr[r] + pv.z;
            o[r][3] = o[r][3] * corr[r] + pv.w;
        }
        __syncthreads();
    }

    const int b_ = bh >> 4;
    const int hh = bh & 15;
    __nv_bfloat16* oh = (__nv_bfloat16*)g_attn;
    __nv_bfloat16* ol = oh + ATT_PLANE;
#pragma unroll
    for (int r = 0; r < 8; r++) {
        float inv = 1.0f / l_r[r];
        int n = q0 + ty * 8 + r;
        const size_t off = ((size_t)b_ * SEQ + n) * EMBED + hh * 64 + tx * 4;
        float v0 = o[r][0] * inv, v1 = o[r][1] * inv;
        float v2 = o[r][2] * inv, v3 = o[r][3] * inv;
        __nv_bfloat16 h0, l0, h1, l1, h2, l2, h3, l3;
        sp_bf16(v0, h0, l0); sp_bf16(v1, h1, l1);
        sp_bf16(v2, h2, l2); sp_bf16(v3, h3, l3);
        *(__nv_bfloat162*)(oh + off)     = __nv_bfloat162(h0, h1);
        *(__nv_bfloat162*)(oh + off + 2) = __nv_bfloat162(h2, h3);
        *(__nv_bfloat162*)(ol + off)     = __nv_bfloat162(l0, l1);
        *(__nv_bfloat162*)(ol + off + 2) = __nv_bfloat162(l2, l3);
    }
}

// ---------------------------------------------------------------------------
extern "C" void kernel_launch(void* const* d_in, const int* in_sizes, int n_in,
                              void* d_out, int out_size)
{
    (void)in_sizes; (void)n_in; (void)out_size;
    const float* x     = (const float*)d_in[0];
    const float* qkv_w = (const float*)d_in[1];
    const float* qkv_b = (const float*)d_in[2];
    const float* out_w = (const float*)d_in[3];
    const float* out_b = (const float*)d_in[4];
    float* out = (float*)d_out;

    cudaFuncSetAttribute(gemm_qkv,
                         cudaFuncAttributeMaxDynamicSharedMemorySize, GEMM_SMEM);
    cudaFuncSetAttribute(gemm_proj,
                         cudaFuncAttributeMaxDynamicSharedMemorySize, GEMM_SMEM);
    cudaFuncSetAttribute(attn_wmma,
                         cudaFuncAttributeMaxDynamicSharedMemorySize,
                         ATTN_SMEM_BYTES);

    static void* p_attn = nullptr;
    static void* p_q = nullptr;
    if (!p_attn) {
        cudaGetSymbolAddress(&p_attn, g_attn);
        cudaGetSymbolAddress(&p_q, g_q);
    }
    __nv_bfloat16* wq_h = (__nv_bfloat16*)p_attn;
    __nv_bfloat16* wq_l = wq_h + 3 * EMBED * EMBED;
    __nv_bfloat16* wo_h = (__nv_bfloat16*)p_q;
    __nv_bfloat16* wo_l = wo_h + EMBED * EMBED;

    // 0) split qkv_w into planes parked in g_attn
    split_w<<<3 * EMBED * EMBED / 1024, 256>>>(qkv_w, wq_h, wq_l);

    // 1) QKV projection (64x128 tiles, 2 CTAs/SM)
    gemm_qkv<<<dim3(3 * EMBED / 128, MTOK / 64), 128, GEMM_SMEM>>>(
        x, wq_h, qkv_b);

    // 2) Flash attention (reads q/k/v planes) -> O planes in g_attn
    attn_wmma<<<dim3(SEQ / 128, BATCH * NHEADS), 256, ATTN_SMEM_BYTES>>>();

    // 3) split out_w into g_q (dead after attention), then projection
    split_w<<<EMBED * EMBED / 1024, 256>>>(out_w, wo_h, wo_l);
    gemm_proj<<<dim3(EMBED / 128, MTOK / 64), 128, GEMM_SMEM>>>(
        (const __nv_bfloat16*)p_attn, wo_h, out_b, out);
}

// round 15
// speedup vs baseline: 1.1608x; 1.1608x over previous
#include <cuda_runtime.h>
#include <cuda_bf16.h>
#include <cuda_pipeline.h>
#include <mma.h>
#include <cstdint>

using namespace nvcuda;

// Problem constants
#define EMBED  1024
#define NHEADS 16
#define HDIM   64
#define BATCH  4
#define SEQ    2048
#define MTOK   (BATCH * SEQ)   // 8192
#define QKV_PLANE (BATCH * NHEADS * SEQ * HDIM)   // 8388608 elems
#define ATT_PLANE (MTOK * EMBED)                  // 8388608 elems

// ---------------------------------------------------------------------------
// Scratch — proven-safe 128 MB footprint, planes recycled (R13 scheme).
// ---------------------------------------------------------------------------
__device__ float g_q[QKV_PLANE];
__device__ float g_k[QKV_PLANE];
__device__ float g_v[QKV_PLANE];
__device__ float g_attn[ATT_PLANE];

__device__ __forceinline__ void sp_bf16(float x, __nv_bfloat16& h, __nv_bfloat16& l)
{
    h = __float2bfloat16_rn(x);
    l = __float2bfloat16_rn(x - __bfloat162float(h));
}

__device__ __forceinline__ void st_split4(
    __nv_bfloat16* H, __nv_bfloat16* L, int off, float4 v)
{
    __nv_bfloat16 hx, lx, hy, ly, hz, lz, hw, lw;
    sp_bf16(v.x, hx, lx); sp_bf16(v.y, hy, ly);
    sp_bf16(v.z, hz, lz); sp_bf16(v.w, hw, lw);
    *(__nv_bfloat162*)(H + off)     = __nv_bfloat162(hx, hy);
    *(__nv_bfloat162*)(H + off + 2) = __nv_bfloat162(hz, hw);
    *(__nv_bfloat162*)(L + off)     = __nv_bfloat162(lx, ly);
    *(__nv_bfloat162*)(L + off + 2) = __nv_bfloat162(lz, lw);
}

__global__ __launch_bounds__(256) void split_w(
    const float* __restrict__ src,
    __nv_bfloat16* __restrict__ hp, __nv_bfloat16* __restrict__ lp)
{
    int i = blockIdx.x * 256 + threadIdx.x;
    float4 v = ((const float4*)src)[i];
    st_split4(hp, lp, 4 * i, v);
}

// ---------------------------------------------------------------------------
// GEMM geometry (R13): block 128x128, BK=32, 256 threads, 8 warps (wm0..3,
// wn0..1) each 32x64. Double-buffered smem, plane loads via cp.async.
// ---------------------------------------------------------------------------
#define LDSG  40
#define MATG  (128 * LDSG)
#define BUFG  (4 * MATG)
#define GEMM_SMEM (2 * BUFG * 2 + 8 * 16 * 20 * 4)   // 92160 B
#define NKBG  (EMBED / 32)

// ---------------------------------------------------------------------------
// QKV GEMM: A = x fp32 (reg-prefetch + in-kernel split), B = pre-split
// planes via __pipeline_memcpy_async. Epilogue -> hi/lo planes in g_q/g_k/g_v.
// ---------------------------------------------------------------------------
__global__ __launch_bounds__(256) void gemm_qkv(
    const float* __restrict__ A, const __nv_bfloat16* __restrict__ Wh,
    const float* __restrict__ bias)
{
    extern __shared__ __align__(16) char dsm[];
    __nv_bfloat16* sm0 = (__nv_bfloat16*)dsm;
    float* sPatchAll   = (float*)(dsm + 2 * BUFG * 2);

    const __nv_bfloat16* Wl = Wh + 3 * EMBED * EMBED;

    const int tid  = threadIdx.x;
    const int lane = tid & 31;
    const int w    = tid >> 5;
    const int wm   = w & 3;
    const int wn   = w >> 2;
    const int m0   = blockIdx.y * 128;
    const int n0   = blockIdx.x * 128;

    const int lrow = tid >> 1;
    const int lseg = (tid & 1) * 16;
    const float* gA = A + (size_t)(m0 + lrow) * EMBED + lseg;
    const __nv_bfloat16* gWh = Wh + (size_t)(n0 + lrow) * EMBED + lseg;
    const __nv_bfloat16* gWl = Wl + (size_t)(n0 + lrow) * EMBED + lseg;
    const int off = lrow * LDSG + lseg;

    wmma::fragment<wmma::accumulator, 16, 16, 16, float> acc[2][4];
#pragma unroll
    for (int mt = 0; mt < 2; mt++)
#pragma unroll
        for (int nt = 0; nt < 4; nt++)
            wmma::fill_fragment(acc[mt][nt], 0.0f);

    float4 pa[4];

    // prologue: B planes kb=0 async; A kb=0 via regs + split-store
    {
        __nv_bfloat16* bBh = sm0 + 2 * MATG;
        __nv_bfloat16* bBl = sm0 + 3 * MATG;
        __pipeline_memcpy_async(bBh + off,     gWh,     16);
        __pipeline_memcpy_async(bBh + off + 8, gWh + 8, 16);
        __pipeline_memcpy_async(bBl + off,     gWl,     16);
        __pipeline_memcpy_async(bBl + off + 8, gWl + 8, 16);
        __pipeline_commit();
#pragma unroll
        for (int j = 0; j < 4; j++) pa[j] = *(const float4*)(gA + 4 * j);
        __nv_bfloat16* bAh = sm0;
        __nv_bfloat16* bAl = sm0 + MATG;
#pragma unroll
        for (int j = 0; j < 4; j++) st_split4(bAh, bAl, off + 4 * j, pa[j]);
        __pipeline_wait_prior(0);
    }
    __syncthreads();

    for (int kb = 0; kb < NKBG; kb++) {
        if (kb + 1 < NKBG) {
            const int g = (kb + 1) * 32;
            __nv_bfloat16* bb = sm0 + ((kb + 1) & 1) * BUFG;
            __nv_bfloat16* bBh = bb + 2 * MATG;
            __nv_bfloat16* bBl = bb + 3 * MATG;
            __pipeline_memcpy_async(bBh + off,     gWh + g,     16);
            __pipeline_memcpy_async(bBh + off + 8, gWh + g + 8, 16);
            __pipeline_memcpy_async(bBl + off,     gWl + g,     16);
            __pipeline_memcpy_async(bBl + off + 8, gWl + g + 8, 16);
            __pipeline_commit();
#pragma unroll
            for (int j = 0; j < 4; j++) pa[j] = *(const float4*)(gA + g + 4 * j);
        }

        const __nv_bfloat16* sb  = sm0 + (kb & 1) * BUFG;
        const __nv_bfloat16* sAh = sb;
        const __nv_bfloat16* sAl = sb + MATG;
        const __nv_bfloat16* sBh = sb + 2 * MATG;
        const __nv_bfloat16* sBl = sb + 3 * MATG;
#pragma unroll
        for (int ks = 0; ks < 2; ks++) {
            const int kk = ks * 16;
            wmma::fragment<wmma::matrix_a, 16, 16, 16, __nv_bfloat16,
                           wmma::row_major> ah[2], al[2];
#pragma unroll
            for (int mt = 0; mt < 2; mt++) {
                wmma::load_matrix_sync(ah[mt], sAh + (wm * 32 + mt * 16) * LDSG + kk, LDSG);
                wmma::load_matrix_sync(al[mt], sAl + (wm * 32 + mt * 16) * LDSG + kk, LDSG);
            }
#pragma unroll
            for (int nt = 0; nt < 4; nt++) {
                wmma::fragment<wmma::matrix_b, 16, 16, 16, __nv_bfloat16,
                               wmma::col_major> bh, bl;
                wmma::load_matrix_sync(bh, sBh + (wn * 64 + nt * 16) * LDSG + kk, LDSG);
                wmma::load_matrix_sync(bl, sBl + (wn * 64 + nt * 16) * LDSG + kk, LDSG);
#pragma unroll
                for (int mt = 0; mt < 2; mt++) {
                    wmma::mma_sync(acc[mt][nt], ah[mt], bh, acc[mt][nt]);
                    wmma::mma_sync(acc[mt][nt], ah[mt], bl, acc[mt][nt]);
                    wmma::mma_sync(acc[mt][nt], al[mt], bh, acc[mt][nt]);
                }
            }
        }

        if (kb + 1 < NKBG) {
            __nv_bfloat16* bb  = sm0 + ((kb + 1) & 1) * BUFG;
            __nv_bfloat16* bAh = bb;
            __nv_bfloat16* bAl = bb + MATG;
#pragma unroll
            for (int j = 0; j < 4; j++) st_split4(bAh, bAl, off + 4 * j, pa[j]);
            __pipeline_wait_prior(0);
            __syncthreads();
        }
    }

    // Epilogue: bias, then bf16 hi/lo planes into g_q/g_k/g_v
    float* patch = sPatchAll + w * 320;
    const int pr = lane >> 1;
    const int pc = (lane & 1) * 8;
#pragma unroll
    for (int mt = 0; mt < 2; mt++)
#pragma unroll
        for (int nt = 0; nt < 4; nt++) {
            wmma::store_matrix_sync(patch, acc[mt][nt], 20, wmma::mem_row_major);
            __syncwarp();
            const int m = m0 + wm * 32 + mt * 16 + pr;
            const int n = n0 + wn * 64 + nt * 16 + pc;
            float f[8];
#pragma unroll
            for (int j = 0; j < 8; j++)
                f[j] = patch[pr * 20 + pc + j] + bias[n + j];
            const int b_ = m >> 11, nq = m & (SEQ - 1);
            const int which = n >> 10, e = n & 1023;
            const int h = e >> 6, d = e & 63;
            float* base = (which == 0) ? g_q : (which == 1) ? g_k : g_v;
            __nv_bfloat16* hp = (__nv_bfloat16*)base;
            __nv_bfloat16* lp = hp + QKV_PLANE;
            const size_t goff = ((((size_t)b_ * NHEADS) + h) * SEQ + nq) * HDIM + d;
#pragma unroll
            for (int j = 0; j < 8; j += 2) {
                __nv_bfloat16 h0, l0, h1, l1;
                sp_bf16(f[j], h0, l0);
                sp_bf16(f[j + 1], h1, l1);
                *(__nv_bfloat162*)(hp + goff + j) = __nv_bfloat162(h0, h1);
                *(__nv_bfloat162*)(lp + goff + j) = __nv_bfloat162(l0, l1);
            }
            __syncwarp();
        }
}

// ---------------------------------------------------------------------------
// Output-proj GEMM: ALL operands pre-split planes -> full cp.async pipeline.
// ---------------------------------------------------------------------------
__global__ __launch_bounds__(256) void gemm_proj(
    const __nv_bfloat16* __restrict__ Ah, const __nv_bfloat16* __restrict__ Wh,
    const float* __restrict__ bias, float* __restrict__ C)
{
    extern __shared__ __align__(16) char dsm[];
    __nv_bfloat16* sm0 = (__nv_bfloat16*)dsm;
    float* sPatchAll   = (float*)(dsm + 2 * BUFG * 2);

    const __nv_bfloat16* Al = Ah + ATT_PLANE;
    const __nv_bfloat16* Wl = Wh + EMBED * EMBED;

    const int tid  = threadIdx.x;
    const int lane = tid & 31;
    const int w    = tid >> 5;
    const int wm   = w & 3;
    const int wn   = w >> 2;
    const int m0   = blockIdx.y * 128;
    const int n0   = blockIdx.x * 128;

    const int lrow = tid >> 1;
    const int lseg = (tid & 1) * 16;
    const __nv_bfloat16* gAh = Ah + (size_t)(m0 + lrow) * EMBED + lseg;
    const __nv_bfloat16* gAl = Al + (size_t)(m0 + lrow) * EMBED + lseg;
    const __nv_bfloat16* gWh = Wh + (size_t)(n0 + lrow) * EMBED + lseg;
    const __nv_bfloat16* gWl = Wl + (size_t)(n0 + lrow) * EMBED + lseg;
    const int off = lrow * LDSG + lseg;

    wmma::fragment<wmma::accumulator, 16, 16, 16, float> acc[2][4];
#pragma unroll
    for (int mt = 0; mt < 2; mt++)
#pragma unroll
        for (int nt = 0; nt < 4; nt++)
            wmma::fill_fragment(acc[mt][nt], 0.0f);

    // async-copy one k-block's 4 planes into buffer bb at global offset g
    auto issue = [&](__nv_bfloat16* bb, int g) {
        __pipeline_memcpy_async(bb + off,                  gAh + g,     16);
        __pipeline_memcpy_async(bb + off + 8,              gAh + g + 8, 16);
        __pipeline_memcpy_async(bb + MATG + off,           gAl + g,     16);
        __pipeline_memcpy_async(bb + MATG + off + 8,       gAl + g + 8, 16);
        __pipeline_memcpy_async(bb + 2 * MATG + off,       gWh + g,     16);
        __pipeline_memcpy_async(bb + 2 * MATG + off + 8,   gWh + g + 8, 16);
        __pipeline_memcpy_async(bb + 3 * MATG + off,       gWl + g,     16);
        __pipeline_memcpy_async(bb + 3 * MATG + off + 8,   gWl + g + 8, 16);
        __pipeline_commit();
    };

    issue(sm0, 0);
    __pipeline_wait_prior(0);
    __syncthreads();

    for (int kb = 0; kb < NKBG; kb++) {
        if (kb + 1 < NKBG)
            issue(sm0 + ((kb + 1) & 1) * BUFG, (kb + 1) * 32);

        const __nv_bfloat16* sb  = sm0 + (kb & 1) * BUFG;
        const __nv_bfloat16* sAh = sb;
        const __nv_bfloat16* sAl = sb + MATG;
        const __nv_bfloat16* sBh = sb + 2 * MATG;
        const __nv_bfloat16* sBl = sb + 3 * MATG;
#pragma unroll
        for (int ks = 0; ks < 2; ks++) {
            const int kk = ks * 16;
            wmma::fragment<wmma::matrix_a, 16, 16, 16, __nv_bfloat16,
                           wmma::row_major> ah[2], al[2];
#pragma unroll
            for (int mt = 0; mt < 2; mt++) {
                wmma::load_matrix_sync(ah[mt], sAh + (wm * 32 + mt * 16) * LDSG + kk, LDSG);
                wmma::load_matrix_sync(al[mt], sAl + (wm * 32 + mt * 16) * LDSG + kk, LDSG);
            }
#pragma unroll
            for (int nt = 0; nt < 4; nt++) {
                wmma::fragment<wmma::matrix_b, 16, 16, 16, __nv_bfloat16,
                               wmma::col_major> bh, bl;
                wmma::load_matrix_sync(bh, sBh + (wn * 64 + nt * 16) * LDSG + kk, LDSG);
                wmma::load_matrix_sync(bl, sBl + (wn * 64 + nt * 16) * LDSG + kk, LDSG);
#pragma unroll
                for (int mt = 0; mt < 2; mt++) {
                    wmma::mma_sync(acc[mt][nt], ah[mt], bh, acc[mt][nt]);
                    wmma::mma_sync(acc[mt][nt], ah[mt], bl, acc[mt][nt]);
                    wmma::mma_sync(acc[mt][nt], al[mt], bh, acc[mt][nt]);
                }
            }
        }

        if (kb + 1 < NKBG) {
            __pipeline_wait_prior(0);
            __syncthreads();
        }
    }

    float* patch = sPatchAll + w * 320;
    const int pr = lane >> 1;
    const int pc = (lane & 1) * 8;
#pragma unroll
    for (int mt = 0; mt < 2; mt++)
#pragma unroll
        for (int nt = 0; nt < 4; nt++) {
            wmma::store_matrix_sync(patch, acc[mt][nt], 20, wmma::mem_row_major);
            __syncwarp();
            const int m = m0 + wm * 32 + mt * 16 + pr;
            const int n = n0 + wn * 64 + nt * 16 + pc;
            float4 q0 = *(const float4*)&patch[pr * 20 + pc];
            float4 q1 = *(const float4*)&patch[pr * 20 + pc + 4];
            float4 b0 = *(const float4*)&bias[n];
            float4 b1 = *(const float4*)&bias[n + 4];
            q0.x += b0.x; q0.y += b0.y; q0.z += b0.z; q0.w += b0.w;
            q1.x += b1.x; q1.y += b1.y; q1.z += b1.z; q1.w += b1.w;
            float* p = C + (size_t)m * EMBED + n;
            *(float4*)(p)     = q0;
            *(float4*)(p + 4) = q1;
            __syncwarp();
        }
}

// ---------------------------------------------------------------------------
// WMMA flash attention — byte-identical to Round 13 (passing).
// ---------------------------------------------------------------------------
#define OFF_QH 0
#define OFF_QL 18432
#define OFF_KH 36864
#define OFF_KL 55296
#define OFF_VH 73728
#define OFF_VL 92160
#define OFF_S  110592
#define OFF_PH 110592
#define OFF_PL 145408
#define OFF_OS 180224
#define ATTN_SMEM_BYTES 215040

__global__ __launch_bounds__(256, 1) void attn_wmma()
{
    extern __shared__ char smc[];
    __nv_bfloat16* Qh = (__nv_bfloat16*)(smc + OFF_QH);
    __nv_bfloat16* Ql = (__nv_bfloat16*)(smc + OFF_QL);
    __nv_bfloat16* Kh = (__nv_bfloat16*)(smc + OFF_KH);
    __nv_bfloat16* Kl = (__nv_bfloat16*)(smc + OFF_KL);
    __nv_bfloat16* Vh = (__nv_bfloat16*)(smc + OFF_VH);
    __nv_bfloat16* Vl = (__nv_bfloat16*)(smc + OFF_VL);
    float*         S  = (float*)        (smc + OFF_S);
    __nv_bfloat16* Ph = (__nv_bfloat16*)(smc + OFF_PH);
    __nv_bfloat16* Pl = (__nv_bfloat16*)(smc + OFF_PL);
    float*         Os = (float*)        (smc + OFF_OS);

    const int tid  = threadIdx.x;
    const int w    = tid >> 5;
    const int wm   = w & 3;
    const int wn   = w >> 2;
    const int ty   = tid >> 4;
    const int tx   = tid & 15;
    const int bh   = blockIdx.y;
    const int q0   = blockIdx.x * 128;

    const __nv_bfloat16* qh = (const __nv_bfloat16*)g_q;
    const __nv_bfloat16* kh = (const __nv_bfloat16*)g_k;
    const __nv_bfloat16* vh = (const __nv_bfloat16*)g_v;
    const size_t tb = (size_t)bh * SEQ * HDIM;

#pragma unroll
    for (int i = 0; i < 4; i++) {
        int idx = tid + i * 256;
        int r   = idx >> 3;
        int c8  = (idx & 7) * 8;
        size_t g = tb + (size_t)(q0 + r) * HDIM + c8;
        *(uint4*)(Qh + r * 72 + c8) = *(const uint4*)(qh + g);
        *(uint4*)(Ql + r * 72 + c8) = *(const uint4*)(qh + QKV_PLANE + g);
    }

    float m_r[8], l_r[8], corr[8], o[8][4];
#pragma unroll
    for (int i = 0; i < 8; i++) {
        m_r[i] = -1e30f;
        l_r[i] = 0.f;
#pragma unroll
        for (int j = 0; j < 4; j++) o[i][j] = 0.f;
    }
    __syncthreads();

    for (int t = 0; t < SEQ / 128; t++) {
        const int k0 = t * 128;
#pragma unroll
        for (int i = 0; i < 4; i++) {
            int idx = tid + i * 256;
            int r   = idx >> 3;
            int c8  = (idx & 7) * 8;
            size_t g = tb + (size_t)(k0 + r) * HDIM + c8;
            *(uint4*)(Kh + r * 72 + c8) = *(const uint4*)(kh + g);
            *(uint4*)(Kl + r * 72 + c8) = *(const uint4*)(kh + QKV_PLANE + g);
            *(uint4*)(Vh + r * 72 + c8) = *(const uint4*)(vh + g);
            *(uint4*)(Vl + r * 72 + c8) = *(const uint4*)(vh + QKV_PLANE + g);
        }
        __syncthreads();

        {
            wmma::fragment<wmma::accumulator, 16, 16, 16, float> accS[2][4];
#pragma unroll
            for (int mt = 0; mt < 2; mt++)
#pragma unroll
                for (int nt = 0; nt < 4; nt++)
                    wmma::fill_fragment(accS[mt][nt], 0.0f);

#pragma unroll
            for (int kk = 0; kk < 4; kk++) {
                const int k = kk * 16;
                wmma::fragment<wmma::matrix_a, 16, 16, 16, __nv_bfloat16,
                               wmma::row_major> ah[2], al[2];
#pragma unroll
                for (int mt = 0; mt < 2; mt++) {
                    wmma::load_matrix_sync(ah[mt], &Qh[(wm * 32 + mt * 16) * 72 + k], 72);
                    wmma::load_matrix_sync(al[mt], &Ql[(wm * 32 + mt * 16) * 72 + k], 72);
                }
#pragma unroll
                for (int nt = 0; nt < 4; nt++) {
                    wmma::fragment<wmma::matrix_b, 16, 16, 16, __nv_bfloat16,
                                   wmma::col_major> bh2, bl2;
                    wmma::load_matrix_sync(bh2, &Kh[(wn * 64 + nt * 16) * 72 + k], 72);
                    wmma::load_matrix_sync(bl2, &Kl[(wn * 64 + nt * 16) * 72 + k], 72);
#pragma unroll
                    for (int mt = 0; mt < 2; mt++) {
                        wmma::mma_sync(accS[mt][nt], ah[mt], bh2, accS[mt][nt]);
                        wmma::mma_sync(accS[mt][nt], ah[mt], bl2, accS[mt][nt]);
                        wmma::mma_sync(accS[mt][nt], al[mt], bh2, accS[mt][nt]);
                    }
                }
            }
#pragma unroll
            for (int mt = 0; mt < 2; mt++)
#pragma unroll
                for (int nt = 0; nt < 4; nt++)
                    wmma::store_matrix_sync(
                        &S[(wm * 32 + mt * 16) * 136 + wn * 64 + nt * 16],
                        accS[mt][nt], 136, wmma::mem_row_major);
        }
        __syncthreads();

        float s[8][8];
#pragma unroll
        for (int r = 0; r < 8; r++) {
            *(float4*)&s[r][0] = *(const float4*)&S[(ty * 8 + r) * 136 + tx * 8];
            *(float4*)&s[r][4] = *(const float4*)&S[(ty * 8 + r) * 136 + tx * 8 + 4];
        }
#pragma unroll
        for (int r = 0; r < 8; r++) {
            float tmax = -1e30f;
#pragma unroll
            for (int c = 0; c < 8; c++) {
                s[r][c] *= 0.125f;
                tmax = fmaxf(tmax, s[r][c]);
            }
#pragma unroll
            for (int off = 8; off; off >>= 1)
                tmax = fmaxf(tmax, __shfl_xor_sync(0xffffffffu, tmax, off));
            float mnew = fmaxf(m_r[r], tmax);
            corr[r] = __expf(m_r[r] - mnew);
            m_r[r] = mnew;
            float rsum = 0.f;
#pragma unroll
            for (int c = 0; c < 8; c++) {
                float p = __expf(s[r][c] - mnew);
                s[r][c] = p;
                rsum += p;
            }
#pragma unroll
            for (int off = 8; off; off >>= 1)
                rsum += __shfl_xor_sync(0xffffffffu, rsum, off);
            l_r[r] = l_r[r] * corr[r] + rsum;
        }
        __syncthreads();

#pragma unroll
        for (int r = 0; r < 8; r++)
#pragma unroll
            for (int c = 0; c < 8; c++) {
                __nv_bfloat16 h, l;
                sp_bf16(s[r][c], h, l);
                Ph[(ty * 8 + r) * 136 + tx * 8 + c] = h;
                Pl[(ty * 8 + r) * 136 + tx * 8 + c] = l;
            }
        __syncthreads();

        {
            wmma::fragment<wmma::accumulator, 16, 16, 16, float> accO[2][2];
#pragma unroll
            for (int mt = 0; mt < 2; mt++)
#pragma unroll
                for (int nt = 0; nt < 2; nt++)
                    wmma::fill_fragment(accO[mt][nt], 0.0f);

#pragma unroll
            for (int kk = 0; kk < 8; kk++) {
                const int k = kk * 16;
                wmma::fragment<wmma::matrix_a, 16, 16, 16, __nv_bfloat16,
                               wmma::row_major> ph[2], pl[2];
#pragma unroll
                for (int mt = 0; mt < 2; mt++) {
                    wmma::load_matrix_sync(ph[mt], &Ph[(wm * 32 + mt * 16) * 136 + k], 136);
                    wmma::load_matrix_sync(pl[mt], &Pl[(wm * 32 + mt * 16) * 136 + k], 136);
                }
#pragma unroll
                for (int nt = 0; nt < 2; nt++) {
                    wmma::fragment<wmma::matrix_b, 16, 16, 16, __nv_bfloat16,
                                   wmma::row_major> vbh, vbl;
                    wmma::load_matrix_sync(vbh, &Vh[k * 72 + wn * 32 + nt * 16], 72);
                    wmma::load_matrix_sync(vbl, &Vl[k * 72 + wn * 32 + nt * 16], 72);
#pragma unroll
                    for (int mt = 0; mt < 2; mt++) {
                        wmma::mma_sync(accO[mt][nt], ph[mt], vbh, accO[mt][nt]);
                        wmma::mma_sync(accO[mt][nt], ph[mt], vbl, accO[mt][nt]);
                        wmma::mma_sync(accO[mt][nt], pl[mt], vbh, accO[mt][nt]);
                    }
                }
            }
#pragma unroll
            for (int mt = 0; mt < 2; mt++)
#pragma unroll
                for (int nt = 0; nt < 2; nt++)
                    wmma::store_matrix_sync(
                        &Os[(wm * 32 + mt * 16) * 68 + wn * 32 + nt * 16],
                        accO[mt][nt], 68, wmma::mem_row_major);
        }
        __syncthreads();

#pragma unroll
        for (int r = 0; r < 8; r++) {
            float4 pv = *(const float4*)&Os[(ty * 8 + r) * 68 + tx * 4];
            o[r][0] = o[r][0] * corr[r] + pv.x;
            o[r][1] = o[r][1] * corr[r] + pv.y;
            o[r][2] = o[r][2] * corr[r] + pv.z;
            o[r][3] = o[r][3] * corr[r] + pv.w;
        }
        __syncthreads();
    }

    const int b_ = bh >> 4;
    const int hh = bh & 15;
    __nv_bfloat16* oh = (__nv_bfloat16*)g_attn;
    __nv_bfloat16* ol = oh + ATT_PLANE;
#pragma unroll
    for (int r = 0; r < 8; r++) {
        float inv = 1.0f / l_r[r];
        int n = q0 + ty * 8 + r;
        const size_t off = ((size_t)b_ * SEQ + n) * EMBED + hh * 64 + tx * 4;
        float v0 = o[r][0] * inv, v1 = o[r][1] * inv;
        float v2 = o[r][2] * inv, v3 = o[r][3] * inv;
        __nv_bfloat16 h0, l0, h1, l1, h2, l2, h3, l3;
        sp_bf16(v0, h0, l0); sp_bf16(v1, h1, l1);
        sp_bf16(v2, h2, l2); sp_bf16(v3, h3, l3);
        *(__nv_bfloat162*)(oh + off)     = __nv_bfloat162(h0, h1);
        *(__nv_bfloat162*)(oh + off + 2) = __nv_bfloat162(h2, h3);
        *(__nv_bfloat162*)(ol + off)     = __nv_bfloat162(l0, l1);
        *(__nv_bfloat162*)(ol + off + 2) = __nv_bfloat162(l2, l3);
    }
}

// ---------------------------------------------------------------------------
extern "C" void kernel_launch(void* const* d_in, const int* in_sizes, int n_in,
                              void* d_out, int out_size)
{
    (void)in_sizes; (void)n_in; (void)out_size;
    const float* x     = (const float*)d_in[0];
    const float* qkv_w = (const float*)d_in[1];
    const float* qkv_b = (const float*)d_in[2];
    const float* out_w = (const float*)d_in[3];
    const float* out_b = (const float*)d_in[4];
    float* out = (float*)d_out;

    cudaFuncSetAttribute(gemm_qkv,
                         cudaFuncAttributeMaxDynamicSharedMemorySize, GEMM_SMEM);
    cudaFuncSetAttribute(gemm_proj,
                         cudaFuncAttributeMaxDynamicSharedMemorySize, GEMM_SMEM);
    cudaFuncSetAttribute(attn_wmma,
                         cudaFuncAttributeMaxDynamicSharedMemorySize,
                         ATTN_SMEM_BYTES);

    static void* p_attn = nullptr;
    static void* p_q = nullptr;
    if (!p_attn) {
        cudaGetSymbolAddress(&p_attn, g_attn);
        cudaGetSymbolAddress(&p_q, g_q);
    }
    __nv_bfloat16* wq_h = (__nv_bfloat16*)p_attn;
    __nv_bfloat16* wq_l = wq_h + 3 * EMBED * EMBED;
    __nv_bfloat16* wo_h = (__nv_bfloat16*)p_q;
    __nv_bfloat16* wo_l = wo_h + EMBED * EMBED;

    // 0) split qkv_w into planes parked in g_attn
    split_w<<<3 * EMBED * EMBED / 1024, 256>>>(qkv_w, wq_h, wq_l);

    // 1) QKV projection (128x128 tiles, B via cp.async)
    gemm_qkv<<<dim3(3 * EMBED / 128, MTOK / 128), 256, GEMM_SMEM>>>(
        x, wq_h, qkv_b);

    // 2) Flash attention (reads q/k/v planes) -> O planes in g_attn
    attn_wmma<<<dim3(SEQ / 128, BATCH * NHEADS), 256, ATTN_SMEM_BYTES>>>();

    // 3) split out_w into g_q (dead after attention), then projection
    split_w<<<EMBED * EMBED / 1024, 256>>>(out_w, wo_h, wo_l);
    gemm_proj<<<dim3(EMBED / 128, MTOK / 128), 256, GEMM_SMEM>>>(
        (const __nv_bfloat16*)p_attn, wo_h, out_b, out);
}

// round 16
// speedup vs baseline: 1.1966x; 1.0308x over previous
#include <cuda_runtime.h>
#include <cuda_bf16.h>
#include <cuda_pipeline.h>
#include <mma.h>
#include <cstdint>

using namespace nvcuda;

// Problem constants
#define EMBED  1024
#define NHEADS 16
#define HDIM   64
#define BATCH  4
#define SEQ    2048
#define MTOK   (BATCH * SEQ)   // 8192
#define QKV_PLANE (BATCH * NHEADS * SEQ * HDIM)   // 8388608 elems
#define ATT_PLANE (MTOK * EMBED)                  // 8388608 elems

// ---------------------------------------------------------------------------
// Scratch — proven-safe 128 MB footprint, planes recycled (R13 scheme).
// ---------------------------------------------------------------------------
__device__ float g_q[QKV_PLANE];
__device__ float g_k[QKV_PLANE];
__device__ float g_v[QKV_PLANE];
__device__ float g_attn[ATT_PLANE];

__device__ __forceinline__ void sp_bf16(float x, __nv_bfloat16& h, __nv_bfloat16& l)
{
    h = __float2bfloat16_rn(x);
    l = __float2bfloat16_rn(x - __bfloat162float(h));
}

__device__ __forceinline__ void st_split4(
    __nv_bfloat16* H, __nv_bfloat16* L, int off, float4 v)
{
    __nv_bfloat16 hx, lx, hy, ly, hz, lz, hw, lw;
    sp_bf16(v.x, hx, lx); sp_bf16(v.y, hy, ly);
    sp_bf16(v.z, hz, lz); sp_bf16(v.w, hw, lw);
    *(__nv_bfloat162*)(H + off)     = __nv_bfloat162(hx, hy);
    *(__nv_bfloat162*)(H + off + 2) = __nv_bfloat162(hz, hw);
    *(__nv_bfloat162*)(L + off)     = __nv_bfloat162(lx, ly);
    *(__nv_bfloat162*)(L + off + 2) = __nv_bfloat162(lz, lw);
}

__global__ __launch_bounds__(256) void split_w(
    const float* __restrict__ src,
    __nv_bfloat16* __restrict__ hp, __nv_bfloat16* __restrict__ lp)
{
    int i = blockIdx.x * 256 + threadIdx.x;
    float4 v = ((const float4*)src)[i];
    st_split4(hp, lp, 4 * i, v);
}

// ---------------------------------------------------------------------------
// GEMM geometry: block 128x128, BK=32, 512 threads = 16 warps
// (wm = w&3, wn = w>>2; warp tile 32x32, acc[2][2] = 32 regs).
// smem: 2 buffers x 4 matrices x [128][40] bf16 = 81920 B + patch 20480 B.
// ---------------------------------------------------------------------------
#define LDSG  40
#define MATG  (128 * LDSG)
#define BUFG  (4 * MATG)
#define GEMM_SMEM (2 * BUFG * 2 + 16 * 16 * 20 * 4)   // 102400 B
#define NKBG  (EMBED / 32)

// ---------------------------------------------------------------------------
// QKV GEMM: A = x fp32 (reg-stage + in-kernel split), B planes via cp.async.
// Epilogue -> bf16 hi/lo planes in g_q/g_k/g_v.
// ---------------------------------------------------------------------------
__global__ __launch_bounds__(512) void gemm_qkv(
    const float* __restrict__ A, const __nv_bfloat16* __restrict__ Wh,
    const float* __restrict__ bias)
{
    extern __shared__ __align__(16) char dsm[];
    __nv_bfloat16* sm0 = (__nv_bfloat16*)dsm;
    float* sPatchAll   = (float*)(dsm + 2 * BUFG * 2);

    const __nv_bfloat16* Wl = Wh + 3 * EMBED * EMBED;

    const int tid  = threadIdx.x;
    const int lane = tid & 31;
    const int w    = tid >> 5;
    const int wm   = w & 3;
    const int wn   = w >> 2;
    const int m0   = blockIdx.y * 128;
    const int n0   = blockIdx.x * 128;

    // loaders: 4 threads/row, 8 contiguous elems each
    const int lrow = tid >> 2;
    const int lseg = (tid & 3) * 8;
    const float* gA = A + (size_t)(m0 + lrow) * EMBED + lseg;
    const __nv_bfloat16* gWh = Wh + (size_t)(n0 + lrow) * EMBED + lseg;
    const __nv_bfloat16* gWl = Wl + (size_t)(n0 + lrow) * EMBED + lseg;
    const int off = lrow * LDSG + lseg;

    wmma::fragment<wmma::accumulator, 16, 16, 16, float> acc[2][2];
#pragma unroll
    for (int mt = 0; mt < 2; mt++)
#pragma unroll
        for (int nt = 0; nt < 2; nt++)
            wmma::fill_fragment(acc[mt][nt], 0.0f);

    float4 pa[2];

    // prologue: B planes kb=0 async; A kb=0 via regs + split-store
    {
        __nv_bfloat16* bBh = sm0 + 2 * MATG;
        __nv_bfloat16* bBl = sm0 + 3 * MATG;
        __pipeline_memcpy_async(bBh + off, gWh, 16);
        __pipeline_memcpy_async(bBl + off, gWl, 16);
        __pipeline_commit();
        pa[0] = *(const float4*)(gA);
        pa[1] = *(const float4*)(gA + 4);
        __nv_bfloat16* bAh = sm0;
        __nv_bfloat16* bAl = sm0 + MATG;
        st_split4(bAh, bAl, off,     pa[0]);
        st_split4(bAh, bAl, off + 4, pa[1]);
        __pipeline_wait_prior(0);
    }
    __syncthreads();

    for (int kb = 0; kb < NKBG; kb++) {
        if (kb + 1 < NKBG) {
            const int g = (kb + 1) * 32;
            __nv_bfloat16* bb = sm0 + ((kb + 1) & 1) * BUFG;
            __pipeline_memcpy_async(bb + 2 * MATG + off, gWh + g, 16);
            __pipeline_memcpy_async(bb + 3 * MATG + off, gWl + g, 16);
            __pipeline_commit();
            pa[0] = *(const float4*)(gA + g);
            pa[1] = *(const float4*)(gA + g + 4);
        }

        const __nv_bfloat16* sb  = sm0 + (kb & 1) * BUFG;
        const __nv_bfloat16* sAh = sb;
        const __nv_bfloat16* sAl = sb + MATG;
        const __nv_bfloat16* sBh = sb + 2 * MATG;
        const __nv_bfloat16* sBl = sb + 3 * MATG;
#pragma unroll
        for (int ks = 0; ks < 2; ks++) {
            const int kk = ks * 16;
            wmma::fragment<wmma::matrix_a, 16, 16, 16, __nv_bfloat16,
                           wmma::row_major> ah[2], al[2];
#pragma unroll
            for (int mt = 0; mt < 2; mt++) {
                wmma::load_matrix_sync(ah[mt], sAh + (wm * 32 + mt * 16) * LDSG + kk, LDSG);
                wmma::load_matrix_sync(al[mt], sAl + (wm * 32 + mt * 16) * LDSG + kk, LDSG);
            }
#pragma unroll
            for (int nt = 0; nt < 2; nt++) {
                wmma::fragment<wmma::matrix_b, 16, 16, 16, __nv_bfloat16,
                               wmma::col_major> bh, bl;
                wmma::load_matrix_sync(bh, sBh + (wn * 32 + nt * 16) * LDSG + kk, LDSG);
                wmma::load_matrix_sync(bl, sBl + (wn * 32 + nt * 16) * LDSG + kk, LDSG);
#pragma unroll
                for (int mt = 0; mt < 2; mt++) {
                    wmma::mma_sync(acc[mt][nt], ah[mt], bh, acc[mt][nt]);
                    wmma::mma_sync(acc[mt][nt], ah[mt], bl, acc[mt][nt]);
                    wmma::mma_sync(acc[mt][nt], al[mt], bh, acc[mt][nt]);
                }
            }
        }

        if (kb + 1 < NKBG) {
            __nv_bfloat16* bb  = sm0 + ((kb + 1) & 1) * BUFG;
            st_split4(bb, bb + MATG, off,     pa[0]);
            st_split4(bb, bb + MATG, off + 4, pa[1]);
            __pipeline_wait_prior(0);
            __syncthreads();
        }
    }

    // Epilogue: bias, then bf16 hi/lo planes into g_q/g_k/g_v
    float* patch = sPatchAll + w * 320;
    const int pr = lane >> 1;
    const int pc = (lane & 1) * 8;
#pragma unroll
    for (int mt = 0; mt < 2; mt++)
#pragma unroll
        for (int nt = 0; nt < 2; nt++) {
            wmma::store_matrix_sync(patch, acc[mt][nt], 20, wmma::mem_row_major);
            __syncwarp();
            const int m = m0 + wm * 32 + mt * 16 + pr;
            const int n = n0 + wn * 32 + nt * 16 + pc;
            float f[8];
#pragma unroll
            for (int j = 0; j < 8; j++)
                f[j] = patch[pr * 20 + pc + j] + bias[n + j];
            const int b_ = m >> 11, nq = m & (SEQ - 1);
            const int which = n >> 10, e = n & 1023;
            const int h = e >> 6, d = e & 63;
            float* base = (which == 0) ? g_q : (which == 1) ? g_k : g_v;
            __nv_bfloat16* hp = (__nv_bfloat16*)base;
            __nv_bfloat16* lp = hp + QKV_PLANE;
            const size_t goff = ((((size_t)b_ * NHEADS) + h) * SEQ + nq) * HDIM + d;
#pragma unroll
            for (int j = 0; j < 8; j += 2) {
                __nv_bfloat16 h0, l0, h1, l1;
                sp_bf16(f[j], h0, l0);
                sp_bf16(f[j + 1], h1, l1);
                *(__nv_bfloat162*)(hp + goff + j) = __nv_bfloat162(h0, h1);
                *(__nv_bfloat162*)(lp + goff + j) = __nv_bfloat162(l0, l1);
            }
            __syncwarp();
        }
}

// ---------------------------------------------------------------------------
// Output-proj GEMM: ALL operands pre-split planes -> full cp.async pipeline.
// ---------------------------------------------------------------------------
__global__ __launch_bounds__(512) void gemm_proj(
    const __nv_bfloat16* __restrict__ Ah, const __nv_bfloat16* __restrict__ Wh,
    const float* __restrict__ bias, float* __restrict__ C)
{
    extern __shared__ __align__(16) char dsm[];
    __nv_bfloat16* sm0 = (__nv_bfloat16*)dsm;
    float* sPatchAll   = (float*)(dsm + 2 * BUFG * 2);

    const __nv_bfloat16* Al = Ah + ATT_PLANE;
    const __nv_bfloat16* Wl = Wh + EMBED * EMBED;

    const int tid  = threadIdx.x;
    const int lane = tid & 31;
    const int w    = tid >> 5;
    const int wm   = w & 3;
    const int wn   = w >> 2;
    const int m0   = blockIdx.y * 128;
    const int n0   = blockIdx.x * 128;

    const int lrow = tid >> 2;
    const int lseg = (tid & 3) * 8;
    const __nv_bfloat16* gAh = Ah + (size_t)(m0 + lrow) * EMBED + lseg;
    const __nv_bfloat16* gAl = Al + (size_t)(m0 + lrow) * EMBED + lseg;
    const __nv_bfloat16* gWh = Wh + (size_t)(n0 + lrow) * EMBED + lseg;
    const __nv_bfloat16* gWl = Wl + (size_t)(n0 + lrow) * EMBED + lseg;
    const int off = lrow * LDSG + lseg;

    wmma::fragment<wmma::accumulator, 16, 16, 16, float> acc[2][2];
#pragma unroll
    for (int mt = 0; mt < 2; mt++)
#pragma unroll
        for (int nt = 0; nt < 2; nt++)
            wmma::fill_fragment(acc[mt][nt], 0.0f);

    auto issue = [&](__nv_bfloat16* bb, int g) {
        __pipeline_memcpy_async(bb + off,            gAh + g, 16);
        __pipeline_memcpy_async(bb + MATG + off,     gAl + g, 16);
        __pipeline_memcpy_async(bb + 2 * MATG + off, gWh + g, 16);
        __pipeline_memcpy_async(bb + 3 * MATG + off, gWl + g, 16);
        __pipeline_commit();
    };

    issue(sm0, 0);
    __pipeline_wait_prior(0);
    __syncthreads();

    for (int kb = 0; kb < NKBG; kb++) {
        if (kb + 1 < NKBG)
            issue(sm0 + ((kb + 1) & 1) * BUFG, (kb + 1) * 32);

        const __nv_bfloat16* sb  = sm0 + (kb & 1) * BUFG;
        const __nv_bfloat16* sAh = sb;
        const __nv_bfloat16* sAl = sb + MATG;
        const __nv_bfloat16* sBh = sb + 2 * MATG;
        const __nv_bfloat16* sBl = sb + 3 * MATG;
#pragma unroll
        for (int ks = 0; ks < 2; ks++) {
            const int kk = ks * 16;
            wmma::fragment<wmma::matrix_a, 16, 16, 16, __nv_bfloat16,
                           wmma::row_major> ah[2], al[2];
#pragma unroll
            for (int mt = 0; mt < 2; mt++) {
                wmma::load_matrix_sync(ah[mt], sAh + (wm * 32 + mt * 16) * LDSG + kk, LDSG);
                wmma::load_matrix_sync(al[mt], sAl + (wm * 32 + mt * 16) * LDSG + kk, LDSG);
            }
#pragma unroll
            for (int nt = 0; nt < 2; nt++) {
                wmma::fragment<wmma::matrix_b, 16, 16, 16, __nv_bfloat16,
                               wmma::col_major> bh, bl;
                wmma::load_matrix_sync(bh, sBh + (wn * 32 + nt * 16) * LDSG + kk, LDSG);
                wmma::load_matrix_sync(bl, sBl + (wn * 32 + nt * 16) * LDSG + kk, LDSG);
#pragma unroll
                for (int mt = 0; mt < 2; mt++) {
                    wmma::mma_sync(acc[mt][nt], ah[mt], bh, acc[mt][nt]);
                    wmma::mma_sync(acc[mt][nt], ah[mt], bl, acc[mt][nt]);
                    wmma::mma_sync(acc[mt][nt], al[mt], bh, acc[mt][nt]);
                }
            }
        }

        if (kb + 1 < NKBG) {
            __pipeline_wait_prior(0);
            __syncthreads();
        }
    }

    float* patch = sPatchAll + w * 320;
    const int pr = lane >> 1;
    const int pc = (lane & 1) * 8;
#pragma unroll
    for (int mt = 0; mt < 2; mt++)
#pragma unroll
        for (int nt = 0; nt < 2; nt++) {
            wmma::store_matrix_sync(patch, acc[mt][nt], 20, wmma::mem_row_major);
            __syncwarp();
            const int m = m0 + wm * 32 + mt * 16 + pr;
            const int n = n0 + wn * 32 + nt * 16 + pc;
            float4 q0 = *(const float4*)&patch[pr * 20 + pc];
            float4 q1 = *(const float4*)&patch[pr * 20 + pc + 4];
            float4 b0 = *(const float4*)&bias[n];
            float4 b1 = *(const float4*)&bias[n + 4];
            q0.x += b0.x; q0.y += b0.y; q0.z += b0.z; q0.w += b0.w;
            q1.x += b1.x; q1.y += b1.y; q1.z += b1.z; q1.w += b1.w;
            float* p = C + (size_t)m * EMBED + n;
            *(float4*)(p)     = q0;
            *(float4*)(p + 4) = q1;
            __syncwarp();
        }
}

// ---------------------------------------------------------------------------
// WMMA flash attention — R13 core; Q/K/V plane loads via cp.async,
// P hi/lo stores vectorized (uint2). Everything else byte-identical.
// ---------------------------------------------------------------------------
#define OFF_QH 0
#define OFF_QL 18432
#define OFF_KH 36864
#define OFF_KL 55296
#define OFF_VH 73728
#define OFF_VL 92160
#define OFF_S  110592
#define OFF_PH 110592
#define OFF_PL 145408
#define OFF_OS 180224
#define ATTN_SMEM_BYTES 215040

__global__ __launch_bounds__(256, 1) void attn_wmma()
{
    extern __shared__ char smc[];
    __nv_bfloat16* Qh = (__nv_bfloat16*)(smc + OFF_QH);
    __nv_bfloat16* Ql = (__nv_bfloat16*)(smc + OFF_QL);
    __nv_bfloat16* Kh = (__nv_bfloat16*)(smc + OFF_KH);
    __nv_bfloat16* Kl = (__nv_bfloat16*)(smc + OFF_KL);
    __nv_bfloat16* Vh = (__nv_bfloat16*)(smc + OFF_VH);
    __nv_bfloat16* Vl = (__nv_bfloat16*)(smc + OFF_VL);
    float*         S  = (float*)        (smc + OFF_S);
    __nv_bfloat16* Ph = (__nv_bfloat16*)(smc + OFF_PH);
    __nv_bfloat16* Pl = (__nv_bfloat16*)(smc + OFF_PL);
    float*         Os = (float*)        (smc + OFF_OS);

    const int tid  = threadIdx.x;
    const int w    = tid >> 5;
    const int wm   = w & 3;
    const int wn   = w >> 2;
    const int ty   = tid >> 4;
    const int tx   = tid & 15;
    const int bh   = blockIdx.y;
    const int q0   = blockIdx.x * 128;

    const __nv_bfloat16* qh = (const __nv_bfloat16*)g_q;
    const __nv_bfloat16* kh = (const __nv_bfloat16*)g_k;
    const __nv_bfloat16* vh = (const __nv_bfloat16*)g_v;
    const size_t tb = (size_t)bh * SEQ * HDIM;

    // Q tile via cp.async plane copies
#pragma unroll
    for (int i = 0; i < 4; i++) {
        int idx = tid + i * 256;
        int r   = idx >> 3;
        int c8  = (idx & 7) * 8;
        size_t g = tb + (size_t)(q0 + r) * HDIM + c8;
        __pipeline_memcpy_async(Qh + r * 72 + c8, qh + g, 16);
        __pipeline_memcpy_async(Ql + r * 72 + c8, qh + QKV_PLANE + g, 16);
    }
    __pipeline_commit();

    float m_r[8], l_r[8], corr[8], o[8][4];
#pragma unroll
    for (int i = 0; i < 8; i++) {
        m_r[i] = -1e30f;
        l_r[i] = 0.f;
#pragma unroll
        for (int j = 0; j < 4; j++) o[i][j] = 0.f;
    }
    __pipeline_wait_prior(0);
    __syncthreads();

    for (int t = 0; t < SEQ / 128; t++) {
        const int k0 = t * 128;
#pragma unroll
        for (int i = 0; i < 4; i++) {
            int idx = tid + i * 256;
            int r   = idx >> 3;
            int c8  = (idx & 7) * 8;
            size_t g = tb + (size_t)(k0 + r) * HDIM + c8;
            __pipeline_memcpy_async(Kh + r * 72 + c8, kh + g, 16);
            __pipeline_memcpy_async(Kl + r * 72 + c8, kh + QKV_PLANE + g, 16);
            __pipeline_memcpy_async(Vh + r * 72 + c8, vh + g, 16);
            __pipeline_memcpy_async(Vl + r * 72 + c8, vh + QKV_PLANE + g, 16);
        }
        __pipeline_commit();
        __pipeline_wait_prior(0);
        __syncthreads();

        {
            wmma::fragment<wmma::accumulator, 16, 16, 16, float> accS[2][4];
#pragma unroll
            for (int mt = 0; mt < 2; mt++)
#pragma unroll
                for (int nt = 0; nt < 4; nt++)
                    wmma::fill_fragment(accS[mt][nt], 0.0f);

#pragma unroll
            for (int kk = 0; kk < 4; kk++) {
                const int k = kk * 16;
                wmma::fragment<wmma::matrix_a, 16, 16, 16, __nv_bfloat16,
                               wmma::row_major> ah[2], al[2];
#pragma unroll
                for (int mt = 0; mt < 2; mt++) {
                    wmma::load_matrix_sync(ah[mt], &Qh[(wm * 32 + mt * 16) * 72 + k], 72);
                    wmma::load_matrix_sync(al[mt], &Ql[(wm * 32 + mt * 16) * 72 + k], 72);
                }
#pragma unroll
                for (int nt = 0; nt < 4; nt++) {
                    wmma::fragment<wmma::matrix_b, 16, 16, 16, __nv_bfloat16,
                                   wmma::col_major> bh2, bl2;
                    wmma::load_matrix_sync(bh2, &Kh[(wn * 64 + nt * 16) * 72 + k], 72);
                    wmma::load_matrix_sync(bl2, &Kl[(wn * 64 + nt * 16) * 72 + k], 72);
#pragma unroll
                    for (int mt = 0; mt < 2; mt++) {
                        wmma::mma_sync(accS[mt][nt], ah[mt], bh2, accS[mt][nt]);
                        wmma::mma_sync(accS[mt][nt], ah[mt], bl2, accS[mt][nt]);
                        wmma::mma_sync(accS[mt][nt], al[mt], bh2, accS[mt][nt]);
                    }
                }
            }
#pragma unroll
            for (int mt = 0; mt < 2; mt++)
#pragma unroll
                for (int nt = 0; nt < 4; nt++)
                    wmma::store_matrix_sync(
                        &S[(wm * 32 + mt * 16) * 136 + wn * 64 + nt * 16],
                        accS[mt][nt], 136, wmma::mem_row_major);
        }
        __syncthreads();

        float s[8][8];
#pragma unroll
        for (int r = 0; r < 8; r++) {
            *(float4*)&s[r][0] = *(const float4*)&S[(ty * 8 + r) * 136 + tx * 8];
            *(float4*)&s[r][4] = *(const float4*)&S[(ty * 8 + r) * 136 + tx * 8 + 4];
        }
#pragma unroll
        for (int r = 0; r < 8; r++) {
            float tmax = -1e30f;
#pragma unroll
            for (int c = 0; c < 8; c++) {
                s[r][c] *= 0.125f;
                tmax = fmaxf(tmax, s[r][c]);
            }
#pragma unroll
            for (int off = 8; off; off >>= 1)
                tmax = fmaxf(tmax, __shfl_xor_sync(0xffffffffu, tmax, off));
            float mnew = fmaxf(m_r[r], tmax);
            corr[r] = __expf(m_r[r] - mnew);
            m_r[r] = mnew;
            float rsum = 0.f;
#pragma unroll
            for (int c = 0; c < 8; c++) {
                float p = __expf(s[r][c] - mnew);
                s[r][c] = p;
                rsum += p;
            }
#pragma unroll
            for (int off = 8; off; off >>= 1)
                rsum += __shfl_xor_sync(0xffffffffu, rsum, off);
            l_r[r] = l_r[r] * corr[r] + rsum;
        }
        __syncthreads();

        // vectorized P hi/lo stores (4 bf16 per uint2)
#pragma unroll
        for (int r = 0; r < 8; r++) {
            uint2 hv, lv;
            __nv_bfloat16 h0, l0, h1, l1;
            sp_bf16(s[r][0], h0, l0); sp_bf16(s[r][1], h1, l1);
            __nv_bfloat162 hp0(h0, h1), lp0(l0, l1);
            sp_bf16(s[r][2], h0, l0); sp_bf16(s[r][3], h1, l1);
            __nv_bfloat162 hp1(h0, h1), lp1(l0, l1);
            hv.x = *(uint32_t*)&hp0; hv.y = *(uint32_t*)&hp1;
            lv.x = *(uint32_t*)&lp0; lv.y = *(uint32_t*)&lp1;
            *(uint2*)&Ph[(ty * 8 + r) * 136 + tx * 8] = hv;
            *(uint2*)&Pl[(ty * 8 + r) * 136 + tx * 8] = lv;
            sp_bf16(s[r][4], h0, l0); sp_bf16(s[r][5], h1, l1);
            __nv_bfloat162 hp2(h0, h1), lp2(l0, l1);
            sp_bf16(s[r][6], h0, l0); sp_bf16(s[r][7], h1, l1);
            __nv_bfloat162 hp3(h0, h1), lp3(l0, l1);
            hv.x = *(uint32_t*)&hp2; hv.y = *(uint32_t*)&hp3;
            lv.x = *(uint32_t*)&lp2; lv.y = *(uint32_t*)&lp3;
            *(uint2*)&Ph[(ty * 8 + r) * 136 + tx * 8 + 4] = hv;
            *(uint2*)&Pl[(ty * 8 + r) * 136 + tx * 8 + 4] = lv;
        }
        __syncthreads();

        {
            wmma::fragment<wmma::accumulator, 16, 16, 16, float> accO[2][2];
#pragma unroll
            for (int mt = 0; mt < 2; mt++)
#pragma unroll
                for (int nt = 0; nt < 2; nt++)
                    wmma::fill_fragment(accO[mt][nt], 0.0f);

#pragma unroll
            for (int kk = 0; kk < 8; kk++) {
                const int k = kk * 16;
                wmma::fragment<wmma::matrix_a, 16, 16, 16, __nv_bfloat16,
                               wmma::row_major> ph[2], pl[2];
#pragma unroll
                for (int mt = 0; mt < 2; mt++) {
                    wmma::load_matrix_sync(ph[mt], &Ph[(wm * 32 + mt * 16) * 136 + k], 136);
                    wmma::load_matrix_sync(pl[mt], &Pl[(wm * 32 + mt * 16) * 136 + k], 136);
                }
#pragma unroll
                for (int nt = 0; nt < 2; nt++) {
                    wmma::fragment<wmma::matrix_b, 16, 16, 16, __nv_bfloat16,
                                   wmma::row_major> vbh, vbl;
                    wmma::load_matrix_sync(vbh, &Vh[k * 72 + wn * 32 + nt * 16], 72);
                    wmma::load_matrix_sync(vbl, &Vl[k * 72 + wn * 32 + nt * 16], 72);
#pragma unroll
                    for (int mt = 0; mt < 2; mt++) {
                        wmma::mma_sync(accO[mt][nt], ph[mt], vbh, accO[mt][nt]);
                        wmma::mma_sync(accO[mt][nt], ph[mt], vbl, accO[mt][nt]);
                        wmma::mma_sync(accO[mt][nt], pl[mt], vbh, accO[mt][nt]);
                    }
                }
            }
#pragma unroll
            for (int mt = 0; mt < 2; mt++)
#pragma unroll
                for (int nt = 0; nt < 2; nt++)
                    wmma::store_matrix_sync(
                        &Os[(wm * 32 + mt * 16) * 68 + wn * 32 + nt * 16],
                        accO[mt][nt], 68, wmma::mem_row_major);
        }
        __syncthreads();

#pragma unroll
        for (int r = 0; r < 8; r++) {
            float4 pv = *(const float4*)&Os[(ty * 8 + r) * 68 + tx * 4];
            o[r][0] = o[r][0] * corr[r] + pv.x;
            o[r][1] = o[r][1] * corr[r] + pv.y;
            o[r][2] = o[r][2] * corr[r] + pv.z;
            o[r][3] = o[r][3] * corr[r] + pv.w;
        }
        __syncthreads();
    }

    const int b_ = bh >> 4;
    const int hh = bh & 15;
    __nv_bfloat16* oh = (__nv_bfloat16*)g_attn;
    __nv_bfloat16* ol = oh + ATT_PLANE;
#pragma unroll
    for (int r = 0; r < 8; r++) {
        float inv = 1.0f / l_r[r];
        int n = q0 + ty * 8 + r;
        const size_t off = ((size_t)b_ * SEQ + n) * EMBED + hh * 64 + tx * 4;
        float v0 = o[r][0] * inv, v1 = o[r][1] * inv;
        float v2 = o[r][2] * inv, v3 = o[r][3] * inv;
        __nv_bfloat16 h0, l0, h1, l1, h2, l2, h3, l3;
        sp_bf16(v0, h0, l0); sp_bf16(v1, h1, l1);
        sp_bf16(v2, h2, l2); sp_bf16(v3, h3, l3);
        *(__nv_bfloat162*)(oh + off)     = __nv_bfloat162(h0, h1);
        *(__nv_bfloat162*)(oh + off + 2) = __nv_bfloat162(h2, h3);
        *(__nv_bfloat162*)(ol + off)     = __nv_bfloat162(l0, l1);
        *(__nv_bfloat162*)(ol + off + 2) = __nv_bfloat162(l2, l3);
    }
}

// ---------------------------------------------------------------------------
extern "C" void kernel_launch(void* const* d_in, const int* in_sizes, int n_in,
                              void* d_out, int out_size)
{
    (void)in_sizes; (void)n_in; (void)out_size;
    const float* x     = (const float*)d_in[0];
    const float* qkv_w = (const float*)d_in[1];
    const float* qkv_b = (const float*)d_in[2];
    const float* out_w = (const float*)d_in[3];
    const float* out_b = (const float*)d_in[4];
    float* out = (float*)d_out;

    cudaFuncSetAttribute(gemm_qkv,
                         cudaFuncAttributeMaxDynamicSharedMemorySize, GEMM_SMEM);
    cudaFuncSetAttribute(gemm_proj,
                         cudaFuncAttributeMaxDynamicSharedMemorySize, GEMM_SMEM);
    cudaFuncSetAttribute(attn_wmma,
                         cudaFuncAttributeMaxDynamicSharedMemorySize,
                         ATTN_SMEM_BYTES);

    static void* p_attn = nullptr;
    static void* p_q = nullptr;
    if (!p_attn) {
        cudaGetSymbolAddress(&p_attn, g_attn);
        cudaGetSymbolAddress(&p_q, g_q);
    }
    __nv_bfloat16* wq_h = (__nv_bfloat16*)p_attn;
    __nv_bfloat16* wq_l = wq_h + 3 * EMBED * EMBED;
    __nv_bfloat16* wo_h = (__nv_bfloat16*)p_q;
    __nv_bfloat16* wo_l = wo_h + EMBED * EMBED;

    // 0) split qkv_w into planes parked in g_attn
    split_w<<<3 * EMBED * EMBED / 1024, 256>>>(qkv_w, wq_h, wq_l);

    // 1) QKV projection (128x128 tiles, 512 threads / 16 warps)
    gemm_qkv<<<dim3(3 * EMBED / 128, MTOK / 128), 512, GEMM_SMEM>>>(
        x, wq_h, qkv_b);

    // 2) Flash attention (reads q/k/v planes) -> O planes in g_attn
    attn_wmma<<<dim3(SEQ / 128, BATCH * NHEADS), 256, ATTN_SMEM_BYTES>>>();

    // 3) split out_w into g_q (dead after attention), then projection
    split_w<<<EMBED * EMBED / 1024, 256>>>(out_w, wo_h, wo_l);
    gemm_proj<<<dim3(EMBED / 128, MTOK / 128), 512, GEMM_SMEM>>>(
        (const __nv_bfloat16*)p_attn, wo_h, out_b, out);
}